// round 8
// baseline (speedup 1.0000x reference)
#include <cuda_runtime.h>
#include <math.h>
#include <stdint.h>

// -------- problem constants --------
#define BSZ   16384
#define INDIM 64
#define DENC  512
#define NE    2048
#define PBAS  12
#define BP    (BSZ*PBAS)          /* 196608 */
#define ZDIM  (INDIM*PBAS)        /* 768    */

// output layout: [loss, x_hat(B*64), perplexity, idx(BP), coeff(BP)]
#define OFF_LOSS  0
#define OFF_XHAT  1
#define OFF_PERP  (1 + BSZ*INDIM)
#define OFF_IDX   (OFF_PERP + 1)
#define OFF_COEFF (OFF_IDX + BP)

// -------- device scratch (static; referenced ONLY from device code) --------
__device__ __align__(16) float  g_h[BSZ*DENC];
__device__ __align__(16) float  g_t[BSZ*DENC];
__device__ __align__(16) float  g_z[BSZ*ZDIM];
__device__ __align__(16) float  g_enorm[NE];
__device__ int    g_idx[BP];
__device__ int    g_counts[NE];
__device__ double g_lossp[2048];

// ======================= zero counts =======================
__global__ void k_zero() {
    int t = blockIdx.x * blockDim.x + threadIdx.x;
    if (t < NE) g_counts[t] = 0;
}

// ======================= GEMM: C = A(MxK)@B(KxN) + bias =======================
// MODE 0: A = arg (x),  C = g_h
// MODE 1: A = g_h,      C = g_t
// MODE 2: A = g_h,      C = g_z
// 128x128 tile, k-tile 32, 256 threads, 8x8 micro-tile. Single k-ascending
// fmaf accumulator per output (deterministic, round-to-nearest).
template<int MODE>
__global__ __launch_bounds__(256, 2)
void k_gemm(const float* __restrict__ Ain, const float* __restrict__ Bm,
            const float* __restrict__ bias, int N, int K) {
    const float* A = (MODE == 0) ? Ain : g_h;
    float*       C = (MODE == 0) ? g_h : ((MODE == 1) ? g_t : g_z);

    __shared__ __align__(16) float sA[32][132];
    __shared__ __align__(16) float sB[32][132];
    const int tid = threadIdx.x;
    const int tx = tid & 15, ty = tid >> 4;
    const int m0 = blockIdx.y * 128;
    const int n0 = blockIdx.x * 128;

    float acc[8][8];
#pragma unroll
    for (int i = 0; i < 8; i++)
#pragma unroll
        for (int j = 0; j < 8; j++) acc[i][j] = 0.0f;

    for (int kt = 0; kt < K; kt += 32) {
        {   // A tile (transposed into sA[k][m])
            int r  = tid >> 3;
            int kq = (tid & 7) << 2;
#pragma unroll
            for (int p = 0; p < 4; p++) {
                const float4 v = *(const float4*)(A + (size_t)(m0 + p*32 + r) * K + kt + kq);
                int m = p*32 + r;
                sA[kq+0][m] = v.x; sA[kq+1][m] = v.y;
                sA[kq+2][m] = v.z; sA[kq+3][m] = v.w;
            }
        }
        {   // B tile sB[k][n]
            int r  = tid >> 5;
            int cq = (tid & 31) << 2;
#pragma unroll
            for (int p = 0; p < 4; p++) {
                const float4 v = *(const float4*)(Bm + (size_t)(kt + p*8 + r) * N + n0 + cq);
                *(float4*)(&sB[p*8 + r][cq]) = v;
            }
        }
        __syncthreads();
#pragma unroll 8
        for (int kk = 0; kk < 32; kk++) {
            float a[8], b[8];
            *(float4*)(a)     = *(const float4*)(&sA[kk][ty*8]);
            *(float4*)(a + 4) = *(const float4*)(&sA[kk][ty*8 + 4]);
            *(float4*)(b)     = *(const float4*)(&sB[kk][tx*8]);
            *(float4*)(b + 4) = *(const float4*)(&sB[kk][tx*8 + 4]);
#pragma unroll
            for (int i = 0; i < 8; i++)
#pragma unroll
                for (int j = 0; j < 8; j++)
                    acc[i][j] = __fmaf_rn(a[i], b[j], acc[i][j]);
        }
        __syncthreads();
    }
#pragma unroll
    for (int i = 0; i < 8; i++) {
        int m = m0 + ty*8 + i;
#pragma unroll
        for (int j = 0; j < 8; j++) {
            int n = n0 + tx*8 + j;
            C[(size_t)m * N + n] = __fadd_rn(acc[i][j], bias[n]);
        }
    }
}

// ======================= h = h + relu(LN(t)*g + beta) =======================
__global__ void k_ln(const float* __restrict__ gw, const float* __restrict__ bw) {
    __shared__ float red[128];
    const int row = blockIdx.x, tid = threadIdx.x;
    const float* tr = g_t + (size_t)row * DENC;
    float*       hr = g_h + (size_t)row * DENC;

    float v[4], hv[4];
#pragma unroll
    for (int c = 0; c < 4; c++) { v[c] = tr[tid + c*128]; hv[c] = hr[tid + c*128]; }

    float s = (v[0] + v[1]) + (v[2] + v[3]);
    red[tid] = s; __syncthreads();
#pragma unroll
    for (int o = 64; o > 0; o >>= 1) { if (tid < o) red[tid] += red[tid + o]; __syncthreads(); }
    float mu = red[0] * (1.0f / 512.0f);
    __syncthreads();

    float s2 = 0.0f;
#pragma unroll
    for (int c = 0; c < 4; c++) { float d = v[c] - mu; s2 = __fadd_rn(s2, __fmul_rn(d, d)); }
    red[tid] = s2; __syncthreads();
#pragma unroll
    for (int o = 64; o > 0; o >>= 1) { if (tid < o) red[tid] += red[tid + o]; __syncthreads(); }
    float var  = red[0] * (1.0f / 512.0f);
    float rstd = 1.0f / sqrtf(__fadd_rn(var, 1e-5f));

#pragma unroll
    for (int c = 0; c < 4; c++) {
        int col = tid + c*128;
        float o = __fadd_rn(__fmul_rn(__fmul_rn(__fsub_rn(v[c], mu), rstd), gw[col]), bw[col]);
        hr[col] = __fadd_rn(hv[c], fmaxf(o, 0.0f));
    }
}

// ======================= codebook squared norms =======================
// square-then-add, ascending (matches sum(x**2) lowering: fl(acc + fl(x*x)))
__global__ void k_enorm(const float* __restrict__ emb) {
    int k = blockIdx.x * blockDim.x + threadIdx.x;
    if (k < NE) {
        const float* e = emb + (size_t)k * 64;
        float s = 0.0f;
        for (int i = 0; i < 64; i++) s = __fadd_rn(s, __fmul_rn(e[i], e[i]));
        g_enorm[k] = s;
    }
}

// ======================= fused distance + argmin =======================
// d = fl( fl(zn + en) - 2*dot ),  dot = strictly k-ascending fmaf chain.
// argmin with lowest-index tie-break via packed u64 key (== jnp.argmin).
#define DN 132
#define DIST_SMEM (((64*DN*2 + 256) * 4) + 128*16*8)
__global__ __launch_bounds__(256, 2)
void k_dist(const float* __restrict__ emb, float* __restrict__ out) {
    extern __shared__ __align__(16) unsigned char smraw[];
    float* sZ = (float*)smraw;                     // [64][DN]
    float* sE = sZ + 64*DN;                        // [64][DN]
    float* zn = sE + 64*DN;                        // [128]
    float* en = zn + 128;                          // [128]
    unsigned long long* skey = (unsigned long long*)(en + 128); // [128][16]

    const int tid = threadIdx.x;
    const int tx = tid & 15, ty = tid >> 4;
    const int m0 = blockIdx.x * 128;

    // load z tile transposed: sZ[k][r]
    {
        int r4 = tid >> 2, q = tid & 3;
#pragma unroll
        for (int p = 0; p < 2; p++) {
            int r = p*64 + r4;
            const float4* src = (const float4*)(g_z + (size_t)(m0 + r) * 64) + q*4;
#pragma unroll
            for (int s = 0; s < 4; s++) {
                float4 v = src[s];
                int k = q*16 + s*4;
                sZ[(k+0)*DN + r] = v.x; sZ[(k+1)*DN + r] = v.y;
                sZ[(k+2)*DN + r] = v.z; sZ[(k+3)*DN + r] = v.w;
            }
        }
    }
    // init per-(row, tx) min slot
#pragma unroll
    for (int i = 0; i < 8; i++)
        skey[(ty*8 + i)*16 + tx] = 0xFFFFFFFFFFFFFFFFull;
    __syncthreads();
    if (tid < 128) {
        float s = 0.0f;
        for (int k = 0; k < 64; k++) {
            float zv = sZ[k*DN + tid];
            s = __fadd_rn(s, __fmul_rn(zv, zv));
        }
        zn[tid] = s;
    }

    for (int ch = 0; ch < 16; ch++) {
        __syncthreads();
        const int c0 = ch * 128;
        {
            int r4 = tid >> 2, q = tid & 3;
#pragma unroll
            for (int p = 0; p < 2; p++) {
                int r = p*64 + r4;
                const float4* src = (const float4*)(emb + (size_t)(c0 + r) * 64) + q*4;
#pragma unroll
                for (int s = 0; s < 4; s++) {
                    float4 v = src[s];
                    int k = q*16 + s*4;
                    sE[(k+0)*DN + r] = v.x; sE[(k+1)*DN + r] = v.y;
                    sE[(k+2)*DN + r] = v.z; sE[(k+3)*DN + r] = v.w;
                }
            }
            if (tid < 128) en[tid] = g_enorm[c0 + tid];
        }
        __syncthreads();

        float acc[8][8];
#pragma unroll
        for (int i = 0; i < 8; i++)
#pragma unroll
            for (int j = 0; j < 8; j++) acc[i][j] = 0.0f;

#pragma unroll 8
        for (int kk = 0; kk < 64; kk++) {
            float a[8], b[8];
            *(float4*)(a)     = *(const float4*)(sZ + kk*DN + ty*8);
            *(float4*)(a + 4) = *(const float4*)(sZ + kk*DN + ty*8 + 4);
            *(float4*)(b)     = *(const float4*)(sE + kk*DN + tx*8);
            *(float4*)(b + 4) = *(const float4*)(sE + kk*DN + tx*8 + 4);
#pragma unroll
            for (int i = 0; i < 8; i++)
#pragma unroll
                for (int j = 0; j < 8; j++)
                    acc[i][j] = __fmaf_rn(a[i], b[j], acc[i][j]);
        }

        float enr[8];
#pragma unroll
        for (int j = 0; j < 8; j++) enr[j] = en[tx*8 + j];
#pragma unroll
        for (int i = 0; i < 8; i++) {
            float znr = zn[ty*8 + i];
            unsigned long long k1 = 0xFFFFFFFFFFFFFFFFull;
#pragma unroll
            for (int j = 0; j < 8; j++) {
                float S = __fadd_rn(znr, enr[j]);                     // fl(zn+en)
                float d = __fsub_rn(S, __fmul_rn(2.0f, acc[i][j]));   // fl(S-2*dot)
                unsigned long long key =
                    ((unsigned long long)__float_as_uint(d) << 32) | (unsigned)(c0 + tx*8 + j);
                if (key < k1) k1 = key;
            }
            unsigned long long* sp = &skey[(ty*8 + i)*16 + tx];
            if (k1 < *sp) *sp = k1;
        }
    }
    __syncthreads();

    // final per-row reduce
    if (tid < 128) {
        int row = tid;
        unsigned long long a1 = 0xFFFFFFFFFFFFFFFFull;
#pragma unroll
        for (int s = 0; s < 16; s++) {
            unsigned long long k = skey[row*16 + s];
            if (k < a1) a1 = k;
        }
        int w = (int)(a1 & 0xFFFFFFFFull);
        g_idx[m0 + row] = w;
        out[OFF_IDX + m0 + row] = (float)w;
        atomicAdd(&g_counts[w], 1);
    }
}

// ======================= per-block pinv solve (warp per block) =======================
__global__ __launch_bounds__(256)
void k_solve(const float* __restrict__ emb, const float* __restrict__ x,
             float* __restrict__ out) {
    __shared__ float  sA[8][12][64];
    __shared__ float  sx[8][64];
    __shared__ double sG[8][12][12];
    __shared__ double sr[8][12];
    __shared__ double sy[8][12];
    __shared__ double sc[8][12];
    __shared__ int    sidx[8][12], sgrp[8][12], smult[8][12], scol[8][12];
    __shared__ int    su[8];
    __shared__ double wls[8];

    const int lane = threadIdx.x & 31;
    const int w    = threadIdx.x >> 5;
    const size_t b = (size_t)blockIdx.x * 8 + w;

    if (lane < 12) sidx[w][lane] = g_idx[b*12 + lane];
    __syncwarp();
    if (lane == 0) {   // dedup (serial, tiny)
        int u = 0;
        for (int j = 0; j < 12; j++) {
            int v = sidx[w][j], q = -1;
            for (int t = 0; t < u; t++)
                if (sidx[w][scol[w][t]] == v) { q = t; break; }
            if (q < 0) { q = u; scol[w][u] = j; smult[w][u] = 0; u++; }
            sgrp[w][j] = q; smult[w][q]++;
        }
        su[w] = u;
    }
    __syncwarp();

    // gather: STE columns A = fl(z + fl(zq - z)); loss from pre-STE zq vs z
    {
        double ls = 0.0;
        const float* zr = g_z + b * 768;
        for (int t = lane; t < 768; t += 32) {
            int j = t >> 6, i = t & 63;
            float a = emb[(size_t)sidx[w][j]*64 + i];
            float z = zr[t];
            double df = (double)a - (double)z;
            ls += df*df;
            sA[w][j][i] = __fadd_rn(z, __fsub_rn(a, z));
        }
#pragma unroll
        for (int o = 16; o; o >>= 1) ls += __shfl_down_sync(0xffffffffu, ls, o);
        if (lane == 0) wls[w] = ls;
    }
    for (int t = lane; t < 64; t += 32) sx[w][t] = x[b*64 + t];
    __syncwarp();

    const int u = su[w];
    const int npair = u*(u+1)/2;
    for (int t = lane; t < npair + u; t += 32) {
        if (t < npair) {
            int qa = 0, rem = t;
            while (rem >= u - qa) { rem -= (u - qa); qa++; }
            int qb = qa + rem;
            const float* ca = sA[w][scol[w][qa]];
            const float* cb = sA[w][scol[w][qb]];
            double s = 0.0;
            for (int k = 0; k < 64; k++) s = fma((double)ca[k], (double)cb[k], s);
            sG[w][qa][qb] = s; sG[w][qb][qa] = s;
        } else {
            int q = t - npair;
            const float* ca = sA[w][scol[w][q]];
            double s = 0.0;
            for (int k = 0; k < 64; k++) s = fma((double)ca[k], (double)sx[w][k], s);
            sr[w][q] = s;
        }
    }
    __syncwarp();

    // fp64 Cholesky (lower, in place)
    for (int p = 0; p < u; p++) {
        if (lane == 0) sG[w][p][p] = sqrt(sG[w][p][p]);
        __syncwarp();
        double lpp = sG[w][p][p];
        if (lane > p && lane < u) sG[w][lane][p] /= lpp;
        __syncwarp();
        int m = u - p - 1;
        int tot = m*(m+1)/2;
        for (int t = lane; t < tot; t += 32) {
            int a = 0, rem = t;
            while (rem >= m - a) { rem -= (m - a); a++; }
            int j = p + 1 + a;
            int i = j + rem;
            sG[w][i][j] -= sG[w][i][p]*sG[w][j][p];
        }
        __syncwarp();
    }
    if (lane == 0) {   // triangular solves (tiny)
        for (int p = 0; p < u; p++) {
            double s = sr[w][p];
            for (int t = 0; t < p; t++) s -= sG[w][p][t]*sy[w][t];
            sy[w][p] = s / sG[w][p][p];
        }
        for (int p = u - 1; p >= 0; p--) {
            double s = sy[w][p];
            for (int t = p + 1; t < u; t++) s -= sG[w][t][p]*sy[w][t];
            sy[w][p] = s / sG[w][p][p];
        }
    }
    __syncwarp();
    // min-norm split across duplicates -> coeff
    if (lane < 12) {
        int q = sgrp[w][lane];
        double c = sy[w][q] / (double)smult[w][q];
        out[OFF_COEFF + b*12 + lane] = (float)c;
        sc[w][lane] = c;
    }
    __syncwarp();
    // x_hat = A @ coeff
    for (int i = lane; i < 64; i += 32) {
        double s = 0.0;
#pragma unroll
        for (int j = 0; j < 12; j++) s = fma((double)sA[w][j][i], sc[w][j], s);
        out[OFF_XHAT + b*64 + i] = (float)s;
    }

    __syncthreads();
    if (threadIdx.x == 0) {
        double s = 0.0;
        for (int k = 0; k < 8; k++) s += wls[k];
        g_lossp[blockIdx.x] = s;
    }
}

// ======================= scalars: loss, perplexity =======================
__global__ void k_final(float* __restrict__ out) {
    __shared__ double red[256];
    const int tid = threadIdx.x;
    double s = 0.0;
    for (int k = tid; k < NE; k += 256) {
        double p = (double)g_counts[k] / (double)BP;
        s += p * log(p + 1e-10);
    }
    red[tid] = s; __syncthreads();
    for (int o = 128; o; o >>= 1) { if (tid < o) red[tid] += red[tid + o]; __syncthreads(); }
    double perp = exp(-red[0]);
    __syncthreads();

    double ls = 0.0;
    for (int k = tid; k < 2048; k += 256) ls += g_lossp[k];
    red[tid] = ls; __syncthreads();
    for (int o = 128; o; o >>= 1) { if (tid < o) red[tid] += red[tid + o]; __syncthreads(); }

    if (tid == 0) {
        out[OFF_PERP] = (float)perp;
        out[OFF_LOSS] = (float)(red[0] * 1.25 / ((double)BP * 64.0));
    }
}

// ======================= launch =======================
extern "C" void kernel_launch(void* const* d_in, const int* in_sizes, int n_in,
                              void* d_out, int out_size) {
    const float* x      = (const float*)d_in[0];
    const float* enc_w1 = (const float*)d_in[1];
    const float* enc_b1 = (const float*)d_in[2];
    const float* res_w  = (const float*)d_in[3];
    const float* res_b  = (const float*)d_in[4];
    const float* res_g  = (const float*)d_in[5];
    const float* res_bt = (const float*)d_in[6];
    const float* enc_w2 = (const float*)d_in[7];
    const float* enc_b2 = (const float*)d_in[8];
    const float* emb    = (const float*)d_in[9];
    float* out = (float*)d_out;

    cudaFuncSetAttribute(k_dist, cudaFuncAttributeMaxDynamicSharedMemorySize, DIST_SMEM);

    k_zero<<<(NE + 255)/256, 256>>>();

    // encoder: Linear(64->512) -> 2x shared ResBlock -> Linear(512->768)
    k_gemm<0><<<dim3(4, 128), 256>>>(x, enc_w1, enc_b1, DENC, INDIM);
    for (int r = 0; r < 2; r++) {
        k_gemm<1><<<dim3(4, 128), 256>>>(nullptr, res_w, res_b, DENC, DENC);
        k_ln<<<BSZ, 128>>>(res_g, res_bt);
    }
    k_gemm<2><<<dim3(6, 128), 256>>>(nullptr, enc_w2, enc_b2, ZDIM, DENC);

    k_enorm<<<NE/128, 128>>>(emb);
    k_dist<<<BP/128, 256, DIST_SMEM>>>(emb, out);
    k_solve<<<BSZ/8, 256>>>(emb, x, out);
    k_final<<<1, 256>>>(out);
}